// round 15
// baseline (speedup 1.0000x reference)
#include <cuda_runtime.h>
#include <cuda_bf16.h>
#include <math.h>
#include <stdint.h>

#ifndef M_PI
#define M_PI 3.14159265358979323846
#endif

#define NIMG 124
#define NSIDE 128
#define NPIX (NSIDE*NSIDE)
#define NTOT (NIMG*NPIX)
#define LAM_C 0.1f
#define NTHR 512
#define SKB 136                 // bf16 tile row stride (halfwords); 272B rows -> ldmatrix conflict-free

#define TILE_B (128*SKB*2)      // 34816 bytes per bf16 tile
#define OFF_QH   0
#define OFF_QL   (OFF_QH  + TILE_B)
#define OFF_QTH  (OFF_QL  + TILE_B)
#define OFF_QTL  (OFF_QTH + TILE_B)
#define OFF_BH   (OFF_QTL + TILE_B)
#define OFF_BL   (OFF_BH  + TILE_B)
#define OFF_LAM  (OFF_BL  + TILE_B)
#define SMEM_BYTES (OFF_LAM + 512)     // 209,408 B

// ---- persistent state (no cudaMalloc allowed) ----
__device__ float g_G1[NTOT];
__device__ float g_G21a[NTOT], g_G21b[NTOT];
__device__ float g_G22a[NTOT], g_G22b[NTOT];
__device__ float g_DhZa[NTOT], g_DhZb[NTOT];
__device__ float g_DvZa[NTOT], g_DvZb[NTOT];
__device__ float g_Z[NTOT];
__device__ __nv_bfloat16 g_Qh[NPIX], g_Ql[NPIX], g_Qth[NPIX], g_Qtl[NPIX];
__device__ float g_lam[NSIDE];

// ======================= init: Q splits + eigenvalues =======================
__global__ void init_q_kernel() {
    int r = blockIdx.x, n = threadIdx.x;
    double inv = 1.0 / 128.0;
    double s1 = sqrt(inv), s2 = sqrt(2.0 * inv);
    float v;
    if (r == 0)        v = (float)s1;
    else if (r < 64)   v = (float)(s2 * cos(2.0 * M_PI * (double)r * (double)n * inv));
    else if (r == 64)  v = (n & 1) ? (float)(-s1) : (float)s1;
    else               v = (float)(s2 * sin(2.0 * M_PI * (double)(r - 64) * (double)n * inv));
    __nv_bfloat16 h = __float2bfloat16(v);
    __nv_bfloat16 l = __float2bfloat16(v - __bfloat162float(h));
    g_Qh[r * NSIDE + n]  = h;  g_Ql[r * NSIDE + n]  = l;
    g_Qth[n * NSIDE + r] = h;  g_Qtl[n * NSIDE + r] = l;
    if (n == 0) {
        int f = (r <= 64) ? r : (r - 64);
        g_lam[r] = (float)(2.0 - 2.0 * cos(2.0 * M_PI * (double)f * inv));
    }
}

__device__ __forceinline__ float shrinkf(float x, float t) {
    return copysignf(fmaxf(fabsf(x) - t, 0.f), x);
}
__device__ __forceinline__ float4 ld4(const float* p) { return *(const float4*)p; }
__device__ __forceinline__ void st4(float* p, float4 v) { *(float4*)p = v; }

__device__ __forceinline__ uint32_t smem_u32(const void* p) {
    uint32_t a;
    asm("{ .reg .u64 t; cvta.to.shared.u64 t, %1; cvt.u32.u64 %0, t; }" : "=r"(a) : "l"(p));
    return a;
}
__device__ __forceinline__ void ldm4(uint32_t* r, uint32_t addr) {
    asm volatile("ldmatrix.sync.aligned.m8n8.x4.shared.b16 {%0,%1,%2,%3}, [%4];"
        : "=r"(r[0]), "=r"(r[1]), "=r"(r[2]), "=r"(r[3]) : "r"(addr));
}
__device__ __forceinline__ void mma16816(float* d, const uint32_t* a, const uint32_t* b) {
    asm volatile("mma.sync.aligned.m16n8k16.row.col.f32.bf16.bf16.f32 "
        "{%0,%1,%2,%3}, {%4,%5,%6,%7}, {%8,%9}, {%0,%1,%2,%3};"
        : "+f"(d[0]), "+f"(d[1]), "+f"(d[2]), "+f"(d[3])
        : "r"(a[0]), "r"(a[1]), "r"(a[2]), "r"(a[3]), "r"(b[0]), "r"(b[1]));
}
// truncation-based hi/lo split: hi = top 16 bits; lo = exact residual truncated.
__device__ __forceinline__ void split_pair(float f0, float f1, uint32_t& hp, uint32_t& lp) {
    uint32_t u0 = __float_as_uint(f0), u1 = __float_as_uint(f1);
    hp = __byte_perm(u0, u1, 0x7632);
    float l0 = f0 - __uint_as_float(u0 & 0xFFFF0000u);
    float l1 = f1 - __uint_as_float(u1 & 0xFFFF0000u);
    lp = __byte_perm(__float_as_uint(l0), __float_as_uint(l1), 0x7632);
}
__device__ __forceinline__ void split_store4(char* BH, char* BL, int r, int c, float4 v) {
    uint32_t h0,h1,l0,l1;
    split_pair(v.x, v.y, h0, l0);
    split_pair(v.z, v.w, h1, l1);
    uint32_t o = (uint32_t)(r * SKB + c) * 2u;
    *(uint2*)(BH + o) = make_uint2(h0, h1);
    *(uint2*)(BL + o) = make_uint2(l0, l1);
}

// ---- fragment bundle for one k16-step of an m32 x n32 warp tile ----
struct Frag { uint32_t Ah[8], Al[8], Bh[8], Bl[8]; };

__device__ __forceinline__ void load_frag(Frag& F, uint32_t aH, uint32_t aL,
                                          uint32_t bH, uint32_t bL, uint32_t k2) {
    const uint32_t T16 = (uint32_t)(16 * SKB * 2);
    ldm4(F.Ah,     aH + k2);
    ldm4(F.Ah + 4, aH + T16 + k2);
    ldm4(F.Al,     aL + k2);
    ldm4(F.Al + 4, aL + T16 + k2);
    ldm4(F.Bh,     bH + k2);
    ldm4(F.Bh + 4, bH + T16 + k2);
    ldm4(F.Bl,     bL + k2);
    ldm4(F.Bl + 4, bL + T16 + k2);
}

// 3 passes of 8 independent MMAs each: accumulator reuse distance = 8
__device__ __forceinline__ void comp_frag(float d[2][4][4], const Frag& F) {
#pragma unroll
    for (int mi = 0; mi < 2; mi++)
#pragma unroll
        for (int j = 0; j < 4; j++)
            mma16816(d[mi][j], F.Ah + 4 * mi, F.Bh + ((j >> 1) << 2) + ((j & 1) << 1));
#pragma unroll
    for (int mi = 0; mi < 2; mi++)
#pragma unroll
        for (int j = 0; j < 4; j++)
            mma16816(d[mi][j], F.Ah + 4 * mi, F.Bl + ((j >> 1) << 2) + ((j & 1) << 1));
#pragma unroll
    for (int mi = 0; mi < 2; mi++)
#pragma unroll
        for (int j = 0; j < 4; j++)
            mma16816(d[mi][j], F.Al + 4 * mi, F.Bh + ((j >> 1) << 2) + ((j & 1) << 1));
}

// ======================= fused whole-problem kernel: 1 CTA per image =======================
extern __shared__ char smem[];

__global__ void __launch_bounds__(NTHR, 1)
hwtv_fused(const float* __restrict__ Y, const float* __restrict__ inW,
           float* __restrict__ out) {
    char* BH = smem + OFF_BH;
    char* BL = smem + OFF_BL;
    float* sLam = (float*)(smem + OFF_LAM);

    int tid = threadIdx.x;
    int w = tid >> 5, lane = tid & 31;
    int base = blockIdx.x * NPIX;
    uint32_t sb = smem_u32(smem);

    // warp tiling: 4x4 grid of m32 x n32 tiles
    int wm = w >> 2, wn = w & 3;
    int g = lane >> 3, r8 = lane & 7;
    uint32_t aoff = (uint32_t)((32 * wm + r8 + (g & 1) * 8) * SKB + (g >> 1) * 8) * 2u;
    uint32_t boff = (uint32_t)((32 * wn + r8 + (g >> 1) * 8) * SKB + (g & 1) * 8) * 2u;
    int drow = 32 * wm + (lane >> 2);
    int dcol = 32 * wn + 2 * (lane & 3);

    // stage Q/Qt bf16 splits into smem tiles; lam
    for (int p = tid; p < NPIX; p += NTHR) {
        int r = p >> 7, c = p & 127;
        uint32_t o = (uint32_t)(r * SKB + c) * 2u;
        *(unsigned short*)(smem + OFF_QH  + o) = __bfloat16_as_ushort(g_Qh[p]);
        *(unsigned short*)(smem + OFF_QL  + o) = __bfloat16_as_ushort(g_Ql[p]);
        *(unsigned short*)(smem + OFF_QTH + o) = __bfloat16_as_ushort(g_Qth[p]);
        *(unsigned short*)(smem + OFF_QTL + o) = __bfloat16_as_ushort(g_Qtl[p]);
    }
    if (tid < 128) sLam[tid] = g_lam[tid];

    // init ADMM state (set "a" arrays; G1 = 0)
    for (int p = tid; p < NPIX; p += NTHR) {
        int i = p >> 7, j = p & 127;
        int idx = base + p;
        float y = Y[idx];
        g_G1[idx] = 0.f; g_G21a[idx] = 0.f; g_G22a[idx] = 0.f;
        g_DhZa[idx] = y - Y[base + (i << 7) + ((j - 1) & 127)];
        g_DvZa[idx] = y - Y[base + (((i - 1) & 127) << 7) + j];
    }
    __syncthreads();

    double m1d = 0.1, m2d = 0.1;

    // ---- pre0: R(0) from init state (G=0, X=Y) ----
    {
        float mu1 = (float)m1d, mu2 = (float)m2d;
        float thr = LAM_C / mu2;
        for (int ch = tid; ch < NPIX / 4; ch += NTHR) {
            int i = ch >> 5, c0 = (ch & 31) * 4;
            int idx = base + (i << 7) + c0;
            float4 dh = ld4(&g_DhZa[idx]), dv = ld4(&g_DvZa[idx]);
            float4 y = ld4(&Y[idx]);
            float4 Ph, Pv;
            Ph.x = mu2 * shrinkf(dh.x, thr); Ph.y = mu2 * shrinkf(dh.y, thr);
            Ph.z = mu2 * shrinkf(dh.z, thr); Ph.w = mu2 * shrinkf(dh.w, thr);
            Pv.x = mu2 * shrinkf(dv.x, thr); Pv.y = mu2 * shrinkf(dv.y, thr);
            Pv.z = mu2 * shrinkf(dv.z, thr); Pv.w = mu2 * shrinkf(dv.w, thr);
            float Ph4 = mu2 * shrinkf(g_DhZa[base + (i << 7) + ((c0 + 4) & 127)], thr);
            float4 dvd = ld4(&g_DvZa[base + (((i + 1) & 127) << 7) + c0]);
            float4 Pvd;
            Pvd.x = mu2 * shrinkf(dvd.x, thr); Pvd.y = mu2 * shrinkf(dvd.y, thr);
            Pvd.z = mu2 * shrinkf(dvd.z, thr); Pvd.w = mu2 * shrinkf(dvd.w, thr);
            float4 R;
            R.x = mu1 * y.x + (Ph.x - Ph.y) + (Pv.x - Pvd.x);
            R.y = mu1 * y.y + (Ph.y - Ph.z) + (Pv.y - Pvd.y);
            R.z = mu1 * y.z + (Ph.z - Ph.w) + (Pv.z - Pvd.z);
            R.w = mu1 * y.w + (Ph.w - Ph4)  + (Pv.w - Pvd.w);
            split_store4(BH, BL, i, c0, R);
        }
        __syncthreads();
    }

    for (int t = 0; t < 20; t++) {
        float mu1 = (float)m1d, mu2 = (float)m2d;
        float mu1n = (float)(m1d * 1.05), mu2n = (float)(m2d * 1.05);
        float inv2 = 1.f / mu2, thr = LAM_C * inv2;
        float inv2n = 1.f / mu2n, thrn = LAM_C * inv2n;
        float* zdst = (t == 19) ? (out + base) : (g_Z + base);

        // ---- 4 tensor stages: C = A · B^T, A in {Q, Qt}, B = previous C ----
#pragma unroll 1
        for (int st = 0; st < 4; st++) {
            uint32_t aHb = sb + ((st < 2) ? OFF_QH : OFF_QTH) + aoff;
            uint32_t aLb = sb + ((st < 2) ? OFF_QL : OFF_QTL) + aoff;
            uint32_t bHb = sb + OFF_BH + boff;
            uint32_t bLb = sb + OFF_BL + boff;

            float d[2][4][4];
#pragma unroll
            for (int mi = 0; mi < 2; mi++)
#pragma unroll
                for (int j = 0; j < 4; j++)
#pragma unroll
                    for (int e = 0; e < 4; e++) d[mi][j][e] = 0.f;

            Frag f0, f1;
            load_frag(f0, aHb, aLb, bHb, bLb, 0);
#pragma unroll
            for (int ks = 0; ks < 8; ks++) {
                if (ks < 7)
                    load_frag((ks & 1) ? f0 : f1, aHb, aLb, bHb, bLb, (uint32_t)(ks + 1) * 32u);
                comp_frag(d, (ks & 1) ? f1 : f0);
            }
            __syncthreads();   // all reads of BH/BL done before overwrite

            if (st < 3) {
                bool filt = (st == 1);
#pragma unroll
                for (int mi = 0; mi < 2; mi++) {
                    int r0 = drow + 16 * mi;
                    float lr0 = filt ? sLam[r0] : 0.f;
                    float lr1 = filt ? sLam[r0 + 8] : 0.f;
#pragma unroll
                    for (int j = 0; j < 4; j++) {
                        int c = dcol + 8 * j;
                        float f0v = d[mi][j][0], f1v = d[mi][j][1];
                        float f2v = d[mi][j][2], f3v = d[mi][j][3];
                        if (filt) {
                            float la = sLam[c], lb = sLam[c + 1];
                            f0v *= 1.f / (mu1 + mu2 * (lr0 + la));
                            f1v *= 1.f / (mu1 + mu2 * (lr0 + lb));
                            f2v *= 1.f / (mu1 + mu2 * (lr1 + la));
                            f3v *= 1.f / (mu1 + mu2 * (lr1 + lb));
                        }
                        uint32_t hp, lp;
                        uint32_t o0 = (uint32_t)(r0 * SKB + c) * 2u;
                        uint32_t o1 = (uint32_t)((r0 + 8) * SKB + c) * 2u;
                        split_pair(f0v, f1v, hp, lp);
                        *(uint32_t*)(BH + o0) = hp; *(uint32_t*)(BL + o0) = lp;
                        split_pair(f2v, f3v, hp, lp);
                        *(uint32_t*)(BH + o1) = hp; *(uint32_t*)(BL + o1) = lp;
                    }
                }
            } else {
#pragma unroll
                for (int mi = 0; mi < 2; mi++) {
                    int r0 = drow + 16 * mi;
#pragma unroll
                    for (int j = 0; j < 4; j++) {
                        int c = dcol + 8 * j;
                        *(float2*)(zdst + r0 * 128 + c)       = make_float2(d[mi][j][0], d[mi][j][1]);
                        *(float2*)(zdst + (r0 + 8) * 128 + c) = make_float2(d[mi][j][2], d[mi][j][3]);
                    }
                }
            }
            __syncthreads();
        }

        if (t == 19) break;

        // ---- fused post(t) + pre(t+1) ----
        const float* DhZo = (t & 1) ? g_DhZb : g_DhZa;
        const float* DvZo = (t & 1) ? g_DvZb : g_DvZa;
        const float* G21o = (t & 1) ? g_G21b : g_G21a;
        const float* G22o = (t & 1) ? g_G22b : g_G22a;
        float* DhZn = (t & 1) ? g_DhZa : g_DhZb;
        float* DvZn = (t & 1) ? g_DvZa : g_DvZb;
        float* G21n = (t & 1) ? g_G21a : g_G21b;
        float* G22n = (t & 1) ? g_G22a : g_G22b;
        const float* Zg = g_Z + base;

        for (int ch = tid; ch < NPIX / 4; ch += NTHR) {
            int i = ch >> 5, c0 = (ch & 31) * 4;
            int idx = base + (i << 7) + c0;
            int idr = base + (i << 7) + ((c0 + 4) & 127);
            int idd = base + (((i + 1) & 127) << 7) + c0;

            // new gradients from Z(t)
            float4 z  = ld4(&Zg[(i << 7) + c0]);
            float  zl = Zg[(i << 7) + ((c0 - 1) & 127)];
            float4 zu = ld4(&Zg[(((i - 1) & 127) << 7) + c0]);
            float4 zd = ld4(&Zg[(((i + 1) & 127) << 7) + c0]);
            float  zr = Zg[(i << 7) + ((c0 + 4) & 127)];
            float4 dh, dv, dvd;
            dh.x = z.x - zl;  dh.y = z.y - z.x;  dh.z = z.z - z.y;  dh.w = z.w - z.z;
            dv.x = z.x - zu.x; dv.y = z.y - zu.y; dv.z = z.z - zu.z; dv.w = z.w - zu.w;
            float dhr = zr - z.w;
            dvd.x = zd.x - z.x; dvd.y = zd.y - z.y; dvd.z = zd.z - z.z; dvd.w = zd.w - z.w;

            // old state
            float4 dho = ld4(&DhZo[idx]), dvo = ld4(&DvZo[idx]);
            float4 g21 = ld4(&G21o[idx]), g22 = ld4(&G22o[idx]);
            float4 g1 = ld4(&g_G1[idx]);
            float4 w4 = ld4(&inW[idx]), y = ld4(&Y[idx]);
            float dho_r = DhZo[idr], g21_r = G21o[idr];
            float4 dvo_d = ld4(&DvZo[idd]), g22_d = ld4(&G22o[idd]);

            // post: recompute U from old state, update G/X
            float4 uh, uv;
            uh.x = shrinkf(dho.x - g21.x * inv2, thr); uh.y = shrinkf(dho.y - g21.y * inv2, thr);
            uh.z = shrinkf(dho.z - g21.z * inv2, thr); uh.w = shrinkf(dho.w - g21.w * inv2, thr);
            uv.x = shrinkf(dvo.x - g22.x * inv2, thr); uv.y = shrinkf(dvo.y - g22.y * inv2, thr);
            uv.z = shrinkf(dvo.z - g22.z * inv2, thr); uv.w = shrinkf(dvo.w - g22.w * inv2, thr);

            float4 x, g1n, g21nv, g22nv;
            x.x = (w4.x * y.x + mu1 * z.x - g1.x) / (w4.x + mu1);
            x.y = (w4.y * y.y + mu1 * z.y - g1.y) / (w4.y + mu1);
            x.z = (w4.z * y.z + mu1 * z.z - g1.z) / (w4.z + mu1);
            x.w = (w4.w * y.w + mu1 * z.w - g1.w) / (w4.w + mu1);
            g1n.x = g1.x + mu1 * (x.x - z.x); g1n.y = g1.y + mu1 * (x.y - z.y);
            g1n.z = g1.z + mu1 * (x.z - z.z); g1n.w = g1.w + mu1 * (x.w - z.w);
            g21nv.x = g21.x + mu2 * (uh.x - dh.x); g21nv.y = g21.y + mu2 * (uh.y - dh.y);
            g21nv.z = g21.z + mu2 * (uh.z - dh.z); g21nv.w = g21.w + mu2 * (uh.w - dh.w);
            g22nv.x = g22.x + mu2 * (uv.x - dv.x); g22nv.y = g22.y + mu2 * (uv.y - dv.y);
            g22nv.z = g22.z + mu2 * (uv.z - dv.z); g22nv.w = g22.w + mu2 * (uv.w - dv.w);

            // halo new-state values (recomputed locally from old state)
            float g21n_r = g21_r + mu2 * (shrinkf(dho_r - g21_r * inv2, thr) - dhr);
            float4 g22n_d;
            g22n_d.x = g22_d.x + mu2 * (shrinkf(dvo_d.x - g22_d.x * inv2, thr) - dvd.x);
            g22n_d.y = g22_d.y + mu2 * (shrinkf(dvo_d.y - g22_d.y * inv2, thr) - dvd.y);
            g22n_d.z = g22_d.z + mu2 * (shrinkf(dvo_d.z - g22_d.z * inv2, thr) - dvd.z);
            g22n_d.w = g22_d.w + mu2 * (shrinkf(dvo_d.w - g22_d.w * inv2, thr) - dvd.w);

            // store new state
            st4(&DhZn[idx], dh); st4(&DvZn[idx], dv);
            st4(&G21n[idx], g21nv); st4(&G22n[idx], g22nv);
            st4(&g_G1[idx], g1n);

            // pre(t+1): shrink with NEW state and next mu
            float4 Ph, Pv, Pvd;
            Ph.x = mu2n * shrinkf(dh.x - g21nv.x * inv2n, thrn) + g21nv.x;
            Ph.y = mu2n * shrinkf(dh.y - g21nv.y * inv2n, thrn) + g21nv.y;
            Ph.z = mu2n * shrinkf(dh.z - g21nv.z * inv2n, thrn) + g21nv.z;
            Ph.w = mu2n * shrinkf(dh.w - g21nv.w * inv2n, thrn) + g21nv.w;
            float Ph4 = mu2n * shrinkf(dhr - g21n_r * inv2n, thrn) + g21n_r;
            Pv.x = mu2n * shrinkf(dv.x - g22nv.x * inv2n, thrn) + g22nv.x;
            Pv.y = mu2n * shrinkf(dv.y - g22nv.y * inv2n, thrn) + g22nv.y;
            Pv.z = mu2n * shrinkf(dv.z - g22nv.z * inv2n, thrn) + g22nv.z;
            Pv.w = mu2n * shrinkf(dv.w - g22nv.w * inv2n, thrn) + g22nv.w;
            Pvd.x = mu2n * shrinkf(dvd.x - g22n_d.x * inv2n, thrn) + g22n_d.x;
            Pvd.y = mu2n * shrinkf(dvd.y - g22n_d.y * inv2n, thrn) + g22n_d.y;
            Pvd.z = mu2n * shrinkf(dvd.z - g22n_d.z * inv2n, thrn) + g22n_d.z;
            Pvd.w = mu2n * shrinkf(dvd.w - g22n_d.w * inv2n, thrn) + g22n_d.w;

            float4 R;
            R.x = mu1n * x.x + g1n.x + (Ph.x - Ph.y) + (Pv.x - Pvd.x);
            R.y = mu1n * x.y + g1n.y + (Ph.y - Ph.z) + (Pv.y - Pvd.y);
            R.z = mu1n * x.z + g1n.z + (Ph.z - Ph.w) + (Pv.z - Pvd.z);
            R.w = mu1n * x.w + g1n.w + (Ph.w - Ph4)  + (Pv.w - Pvd.w);
            split_store4(BH, BL, i, c0, R);
        }
        __syncthreads();

        m1d *= 1.05; m2d *= 1.05;
    }
}

// ======================= launcher =======================
extern "C" void kernel_launch(void* const* d_in, const int* in_sizes, int n_in,
                              void* d_out, int out_size) {
    const float* Y   = (const float*)d_in[0];
    const float* inW = (const float*)d_in[1];
    float* out = (float*)d_out;

    cudaFuncSetAttribute(hwtv_fused, cudaFuncAttributeMaxDynamicSharedMemorySize, SMEM_BYTES);

    init_q_kernel<<<128, 128>>>();
    hwtv_fused<<<NIMG, NTHR, SMEM_BYTES>>>(Y, inW, out);
}

// round 16
// speedup vs baseline: 1.1263x; 1.1263x over previous
#include <cuda_runtime.h>
#include <cuda_bf16.h>
#include <math.h>
#include <stdint.h>

#ifndef M_PI
#define M_PI 3.14159265358979323846
#endif

#define NIMG 124
#define NSIDE 128
#define NPIX (NSIDE*NSIDE)
#define NTOT (NIMG*NPIX)
#define LAM_C 0.1f
#define NTHR 512
#define SKB 136                 // bf16 tile row stride (halfwords)
#define ZPAD 132                // f32 Zbuf row stride

#define TILE_B (128*SKB*2)      // 34816 bytes per bf16 tile
#define OFF_QH   0
#define OFF_QL   (OFF_QH  + TILE_B)
#define OFF_B0H  (OFF_QL  + TILE_B)
#define OFF_B0L  (OFF_B0H + TILE_B)
#define OFF_B1H  (OFF_B0L + TILE_B)
#define OFF_B1L  (OFF_B1H + TILE_B)
#define OFF_LAM  (OFF_B1L + TILE_B)
#define SMEM_BYTES (OFF_LAM + 512)     // 209,408 B

// ---- persistent state (no cudaMalloc allowed) ----
__device__ float g_X[NTOT], g_G1[NTOT], g_G21[NTOT], g_G22[NTOT];
__device__ float g_DhZ[NTOT], g_DvZ[NTOT];
__device__ __nv_bfloat16 g_Qh[NPIX], g_Ql[NPIX];
__device__ float g_lam[NSIDE];

// ======================= init: Q split + eigenvalues =======================
__global__ void init_q_kernel() {
    int r = blockIdx.x, n = threadIdx.x;
    double inv = 1.0 / 128.0;
    double s1 = sqrt(inv), s2 = sqrt(2.0 * inv);
    float v;
    if (r == 0)        v = (float)s1;
    else if (r < 64)   v = (float)(s2 * cos(2.0 * M_PI * (double)r * (double)n * inv));
    else if (r == 64)  v = (n & 1) ? (float)(-s1) : (float)s1;
    else               v = (float)(s2 * sin(2.0 * M_PI * (double)(r - 64) * (double)n * inv));
    __nv_bfloat16 h = __float2bfloat16(v);
    __nv_bfloat16 l = __float2bfloat16(v - __bfloat162float(h));
    g_Qh[r * NSIDE + n] = h;
    g_Ql[r * NSIDE + n] = l;
    if (n == 0) {
        int f = (r <= 64) ? r : (r - 64);
        g_lam[r] = (float)(2.0 - 2.0 * cos(2.0 * M_PI * (double)f * inv));
    }
}

__device__ __forceinline__ float shrinkf(float x, float t) {
    return copysignf(fmaxf(fabsf(x) - t, 0.f), x);
}
__device__ __forceinline__ float4 ld4(const float* p) { return *(const float4*)p; }
__device__ __forceinline__ void st4(float* p, float4 v) { *(float4*)p = v; }

__device__ __forceinline__ uint32_t smem_u32(const void* p) {
    uint32_t a;
    asm("{ .reg .u64 t; cvta.to.shared.u64 t, %1; cvt.u32.u64 %0, t; }" : "=r"(a) : "l"(p));
    return a;
}
__device__ __forceinline__ void ldm4(uint32_t* r, uint32_t addr) {
    asm volatile("ldmatrix.sync.aligned.m8n8.x4.shared.b16 {%0,%1,%2,%3}, [%4];"
        : "=r"(r[0]), "=r"(r[1]), "=r"(r[2]), "=r"(r[3]) : "r"(addr));
}
__device__ __forceinline__ void ldm4t(uint32_t* r, uint32_t addr) {
    asm volatile("ldmatrix.sync.aligned.m8n8.x4.trans.shared.b16 {%0,%1,%2,%3}, [%4];"
        : "=r"(r[0]), "=r"(r[1]), "=r"(r[2]), "=r"(r[3]) : "r"(addr));
}
__device__ __forceinline__ void mma16816(float* d, const uint32_t* a, const uint32_t* b) {
    asm volatile("mma.sync.aligned.m16n8k16.row.col.f32.bf16.bf16.f32 "
        "{%0,%1,%2,%3}, {%4,%5,%6,%7}, {%8,%9}, {%0,%1,%2,%3};"
        : "+f"(d[0]), "+f"(d[1]), "+f"(d[2]), "+f"(d[3])
        : "r"(a[0]), "r"(a[1]), "r"(a[2]), "r"(a[3]), "r"(b[0]), "r"(b[1]));
}
// truncation-based hi/lo split
__device__ __forceinline__ void split_pair(float f0, float f1, uint32_t& hp, uint32_t& lp) {
    uint32_t u0 = __float_as_uint(f0), u1 = __float_as_uint(f1);
    hp = __byte_perm(u0, u1, 0x7632);
    float l0 = f0 - __uint_as_float(u0 & 0xFFFF0000u);
    float l1 = f1 - __uint_as_float(u1 & 0xFFFF0000u);
    lp = __byte_perm(__float_as_uint(l0), __float_as_uint(l1), 0x7632);
}
__device__ __forceinline__ void split_store4(char* BH, char* BL, int r, int c, float4 v) {
    uint32_t h0,h1,l0,l1;
    split_pair(v.x, v.y, h0, l0);
    split_pair(v.z, v.w, h1, l1);
    uint32_t o = (uint32_t)(r * SKB + c) * 2u;
    *(uint2*)(BH + o) = make_uint2(h0, h1);
    *(uint2*)(BL + o) = make_uint2(l0, l1);
}

// ---- fragment bundle for one k16-step of an m32 x n32 warp tile ----
struct Frag { uint32_t Ah[8], Al[8], Bh[8], Bl[8]; };

#define T16 ((uint32_t)(16 * SKB * 2))

// TR=false: A from Q rows (non-trans, addr aoff); TR=true: A = Q^T via trans loads (addr atoff)
template<bool TR>
__device__ __forceinline__ void load_frag(Frag& F, uint32_t aH, uint32_t aL,
                                          uint32_t bH, uint32_t bL, uint32_t ks) {
    uint32_t k2 = ks * 32u;
    if (TR) {
        uint32_t kr = ks * T16;          // k advances rows of Q
        ldm4t(F.Ah,     aH + kr);
        ldm4t(F.Ah + 4, aH + kr + 32u);  // mi=1: +16 cols
        ldm4t(F.Al,     aL + kr);
        ldm4t(F.Al + 4, aL + kr + 32u);
    } else {
        ldm4(F.Ah,     aH + k2);
        ldm4(F.Ah + 4, aH + T16 + k2);   // mi=1: +16 rows
        ldm4(F.Al,     aL + k2);
        ldm4(F.Al + 4, aL + T16 + k2);
    }
    ldm4(F.Bh,     bH + k2);
    ldm4(F.Bh + 4, bH + T16 + k2);
    ldm4(F.Bl,     bL + k2);
    ldm4(F.Bl + 4, bL + T16 + k2);
}

// 3 passes of 8 independent MMAs each: accumulator reuse distance = 8
__device__ __forceinline__ void comp_frag(float d[2][4][4], const Frag& F) {
#pragma unroll
    for (int mi = 0; mi < 2; mi++)
#pragma unroll
        for (int j = 0; j < 4; j++)
            mma16816(d[mi][j], F.Ah + 4 * mi, F.Bh + ((j >> 1) << 2) + ((j & 1) << 1));
#pragma unroll
    for (int mi = 0; mi < 2; mi++)
#pragma unroll
        for (int j = 0; j < 4; j++)
            mma16816(d[mi][j], F.Ah + 4 * mi, F.Bl + ((j >> 1) << 2) + ((j & 1) << 1));
#pragma unroll
    for (int mi = 0; mi < 2; mi++)
#pragma unroll
        for (int j = 0; j < 4; j++)
            mma16816(d[mi][j], F.Al + 4 * mi, F.Bh + ((j >> 1) << 2) + ((j & 1) << 1));
}

template<bool TR>
__device__ __forceinline__ void run_mma(float d[2][4][4], uint32_t aH, uint32_t aL,
                                        uint32_t bH, uint32_t bL) {
    Frag f0, f1;
    load_frag<TR>(f0, aH, aL, bH, bL, 0);
#pragma unroll
    for (int ks = 0; ks < 8; ks++) {
        if (ks < 7)
            load_frag<TR>((ks & 1) ? f0 : f1, aH, aL, bH, bL, (uint32_t)(ks + 1));
        comp_frag(d, (ks & 1) ? f1 : f0);
    }
}

// ======================= fused whole-problem kernel: 1 CTA per image =======================
extern __shared__ char smem[];

__global__ void __launch_bounds__(NTHR, 1)
hwtv_fused(const float* __restrict__ Y, const float* __restrict__ inW,
           float* __restrict__ out) {
    float* sLam = (float*)(smem + OFF_LAM);
    float* Zbuf = (float*)(smem + OFF_B0H);   // Z f32 occupies pair0 (contiguous 69.6KB)

    int tid = threadIdx.x;
    int w = tid >> 5, lane = tid & 31;
    int base = blockIdx.x * NPIX;
    uint32_t sb = smem_u32(smem);

    // warp tiling: 4x4 grid of m32 x n32 tiles
    int wm = w >> 2, wn = w & 3;
    int g = lane >> 3, r8 = lane & 7;
    uint32_t aoff  = (uint32_t)((32 * wm + r8 + (g & 1) * 8) * SKB + (g >> 1) * 8) * 2u;
    // trans A (Q^T): tile (m,k) <- Q rows k, cols m
    uint32_t atoff = (uint32_t)((r8 + (g >> 1) * 8) * SKB + 32 * wm + (g & 1) * 8) * 2u;
    uint32_t boff  = (uint32_t)((32 * wn + r8 + (g >> 1) * 8) * SKB + (g & 1) * 8) * 2u;
    int drow = 32 * wm + (lane >> 2);
    int dcol = 32 * wn + 2 * (lane & 3);

    // stage Q bf16 split into smem tiles; lam
    for (int p = tid; p < NPIX; p += NTHR) {
        int r = p >> 7, c = p & 127;
        uint32_t o = (uint32_t)(r * SKB + c) * 2u;
        *(unsigned short*)(smem + OFF_QH + o) = __bfloat16_as_ushort(g_Qh[p]);
        *(unsigned short*)(smem + OFF_QL + o) = __bfloat16_as_ushort(g_Ql[p]);
    }
    if (tid < 128) sLam[tid] = g_lam[tid];

    // init ADMM state
    for (int p = tid; p < NPIX; p += NTHR) {
        int i = p >> 7, j = p & 127;
        int idx = base + p;
        float y = Y[idx];
        g_X[idx] = y;
        g_G1[idx] = 0.f; g_G21[idx] = 0.f; g_G22[idx] = 0.f;
        g_DhZ[idx] = y - Y[base + (i << 7) + ((j - 1) & 127)];
        g_DvZ[idx] = y - Y[base + (((i - 1) & 127) << 7) + j];
    }
    __syncthreads();

    double m1d = 0.1, m2d = 0.1;
    for (int t = 0; t < 20; t++) {
        float mu1 = (float)m1d, mu2 = (float)m2d;
        float inv2 = 1.f / mu2, thr = LAM_C * inv2;

        // ---- pre: shrink + RHS -> split into pair0 ----
        {
            char* BH = smem + OFF_B0H;
            char* BL = smem + OFF_B0L;
            for (int ch = tid; ch < NPIX / 4; ch += NTHR) {
                int i = ch >> 5, c0 = (ch & 31) * 4;
                int idx = base + (i << 7) + c0;

                float4 dh = ld4(&g_DhZ[idx]), dv = ld4(&g_DvZ[idx]);
                float4 g21 = ld4(&g_G21[idx]), g22 = ld4(&g_G22[idx]);
                float4 x4 = ld4(&g_X[idx]),  g1 = ld4(&g_G1[idx]);

                float4 Ph, Pv;
                Ph.x = mu2 * shrinkf(dh.x - g21.x * inv2, thr) + g21.x;
                Ph.y = mu2 * shrinkf(dh.y - g21.y * inv2, thr) + g21.y;
                Ph.z = mu2 * shrinkf(dh.z - g21.z * inv2, thr) + g21.z;
                Ph.w = mu2 * shrinkf(dh.w - g21.w * inv2, thr) + g21.w;
                Pv.x = mu2 * shrinkf(dv.x - g22.x * inv2, thr) + g22.x;
                Pv.y = mu2 * shrinkf(dv.y - g22.y * inv2, thr) + g22.y;
                Pv.z = mu2 * shrinkf(dv.z - g22.z * inv2, thr) + g22.z;
                Pv.w = mu2 * shrinkf(dv.w - g22.w * inv2, thr) + g22.w;

                int idr = base + (i << 7) + ((c0 + 4) & 127);
                float dh_r = g_DhZ[idr], g21_r = g_G21[idr];
                float Ph4 = mu2 * shrinkf(dh_r - g21_r * inv2, thr) + g21_r;

                int idd = base + (((i + 1) & 127) << 7) + c0;
                float4 dv_d = ld4(&g_DvZ[idd]), g22_d = ld4(&g_G22[idd]);
                float4 Pvd;
                Pvd.x = mu2 * shrinkf(dv_d.x - g22_d.x * inv2, thr) + g22_d.x;
                Pvd.y = mu2 * shrinkf(dv_d.y - g22_d.y * inv2, thr) + g22_d.y;
                Pvd.z = mu2 * shrinkf(dv_d.z - g22_d.z * inv2, thr) + g22_d.z;
                Pvd.w = mu2 * shrinkf(dv_d.w - g22_d.w * inv2, thr) + g22_d.w;

                float4 R;
                R.x = mu1 * x4.x + g1.x + (Ph.x - Ph.y) + (Pv.x - Pvd.x);
                R.y = mu1 * x4.y + g1.y + (Ph.y - Ph.z) + (Pv.y - Pvd.y);
                R.z = mu1 * x4.z + g1.z + (Ph.z - Ph.w) + (Pv.z - Pvd.z);
                R.w = mu1 * x4.w + g1.w + (Ph.w - Ph4)  + (Pv.w - Pvd.w);
                split_store4(BH, BL, i, c0, R);
            }
        }
        __syncthreads();

        // ---- 4 tensor stages: C = A · B^T; pairs bounce 0->1->0->1->0; 1 barrier each ----
#pragma unroll 1
        for (int st = 0; st < 4; st++) {
            int inp = st & 1;                 // 0,1,0,1
            uint32_t bHb = sb + (inp ? OFF_B1H : OFF_B0H) + boff;
            uint32_t bLb = sb + (inp ? OFF_B1L : OFF_B0L) + boff;

            float d[2][4][4];
#pragma unroll
            for (int mi = 0; mi < 2; mi++)
#pragma unroll
                for (int j = 0; j < 4; j++)
#pragma unroll
                    for (int e = 0; e < 4; e++) d[mi][j][e] = 0.f;

            if (st < 2) run_mma<false>(d, sb + OFF_QH + aoff,  sb + OFF_QL + aoff,  bHb, bLb);
            else        run_mma<true >(d, sb + OFF_QH + atoff, sb + OFF_QL + atoff, bHb, bLb);

            if (st < 3) {
                char* BHo = smem + (inp ? OFF_B0H : OFF_B1H);
                char* BLo = smem + (inp ? OFF_B0L : OFF_B1L);
                bool filt = (st == 1);
#pragma unroll
                for (int mi = 0; mi < 2; mi++) {
                    int r0 = drow + 16 * mi;
                    float lr0 = filt ? sLam[r0] : 0.f;
                    float lr1 = filt ? sLam[r0 + 8] : 0.f;
#pragma unroll
                    for (int j = 0; j < 4; j++) {
                        int c = dcol + 8 * j;
                        float f0v = d[mi][j][0], f1v = d[mi][j][1];
                        float f2v = d[mi][j][2], f3v = d[mi][j][3];
                        if (filt) {
                            float la = sLam[c], lb = sLam[c + 1];
                            f0v *= 1.f / (mu1 + mu2 * (lr0 + la));
                            f1v *= 1.f / (mu1 + mu2 * (lr0 + lb));
                            f2v *= 1.f / (mu1 + mu2 * (lr1 + la));
                            f3v *= 1.f / (mu1 + mu2 * (lr1 + lb));
                        }
                        uint32_t hp, lp;
                        uint32_t o0 = (uint32_t)(r0 * SKB + c) * 2u;
                        uint32_t o1 = (uint32_t)((r0 + 8) * SKB + c) * 2u;
                        split_pair(f0v, f1v, hp, lp);
                        *(uint32_t*)(BHo + o0) = hp; *(uint32_t*)(BLo + o0) = lp;
                        split_pair(f2v, f3v, hp, lp);
                        *(uint32_t*)(BHo + o1) = hp; *(uint32_t*)(BLo + o1) = lp;
                    }
                }
            } else if (t == 19) {
                float* ob = out + base;
#pragma unroll
                for (int mi = 0; mi < 2; mi++) {
                    int r0 = drow + 16 * mi;
#pragma unroll
                    for (int j = 0; j < 4; j++) {
                        int c = dcol + 8 * j;
                        *(float2*)(ob + r0 * 128 + c)       = make_float2(d[mi][j][0], d[mi][j][1]);
                        *(float2*)(ob + (r0 + 8) * 128 + c) = make_float2(d[mi][j][2], d[mi][j][3]);
                    }
                }
            } else {
                // Z f32 into pair0 region (stage-3 input was pair1)
#pragma unroll
                for (int mi = 0; mi < 2; mi++) {
                    int r0 = drow + 16 * mi;
#pragma unroll
                    for (int j = 0; j < 4; j++) {
                        int c = dcol + 8 * j;
                        *(float2*)(Zbuf + r0 * ZPAD + c)       = make_float2(d[mi][j][0], d[mi][j][1]);
                        *(float2*)(Zbuf + (r0 + 8) * ZPAD + c) = make_float2(d[mi][j][2], d[mi][j][3]);
                    }
                }
            }
            __syncthreads();
        }

        if (t < 19) {
            // ---- post: gradients of Z (Zbuf) + X/G updates (in place) ----
            for (int ch = tid; ch < NPIX / 4; ch += NTHR) {
                int i = ch >> 5, c0 = (ch & 31) * 4;
                int idx = base + (i << 7) + c0;

                float4 z = ld4(&Zbuf[i * ZPAD + c0]);
                float zl = Zbuf[i * ZPAD + ((c0 - 1) & 127)];
                float4 zu = ld4(&Zbuf[((i - 1) & 127) * ZPAD + c0]);
                float4 dh, dv;
                dh.x = z.x - zl;  dh.y = z.y - z.x;  dh.z = z.z - z.y;  dh.w = z.w - z.z;
                dv.x = z.x - zu.x; dv.y = z.y - zu.y; dv.z = z.z - zu.z; dv.w = z.w - zu.w;

                float4 dho = ld4(&g_DhZ[idx]), dvo = ld4(&g_DvZ[idx]);
                float4 g21 = ld4(&g_G21[idx]), g22 = ld4(&g_G22[idx]);
                float4 g1 = ld4(&g_G1[idx]);
                float4 w4 = ld4(&inW[idx]), y = ld4(&Y[idx]);

                float4 uh, uv;
                uh.x = shrinkf(dho.x - g21.x * inv2, thr); uh.y = shrinkf(dho.y - g21.y * inv2, thr);
                uh.z = shrinkf(dho.z - g21.z * inv2, thr); uh.w = shrinkf(dho.w - g21.w * inv2, thr);
                uv.x = shrinkf(dvo.x - g22.x * inv2, thr); uv.y = shrinkf(dvo.y - g22.y * inv2, thr);
                uv.z = shrinkf(dvo.z - g22.z * inv2, thr); uv.w = shrinkf(dvo.w - g22.w * inv2, thr);

                float4 x, g1n, g21n, g22n;
                x.x = (w4.x * y.x + mu1 * z.x - g1.x) / (w4.x + mu1);
                x.y = (w4.y * y.y + mu1 * z.y - g1.y) / (w4.y + mu1);
                x.z = (w4.z * y.z + mu1 * z.z - g1.z) / (w4.z + mu1);
                x.w = (w4.w * y.w + mu1 * z.w - g1.w) / (w4.w + mu1);
                g1n.x = g1.x + mu1 * (x.x - z.x); g1n.y = g1.y + mu1 * (x.y - z.y);
                g1n.z = g1.z + mu1 * (x.z - z.z); g1n.w = g1.w + mu1 * (x.w - z.w);
                g21n.x = g21.x + mu2 * (uh.x - dh.x); g21n.y = g21.y + mu2 * (uh.y - dh.y);
                g21n.z = g21.z + mu2 * (uh.z - dh.z); g21n.w = g21.w + mu2 * (uh.w - dh.w);
                g22n.x = g22.x + mu2 * (uv.x - dv.x); g22n.y = g22.y + mu2 * (uv.y - dv.y);
                g22n.z = g22.z + mu2 * (uv.z - dv.z); g22n.w = g22.w + mu2 * (uv.w - dv.w);

                st4(&g_DhZ[idx], dh); st4(&g_DvZ[idx], dv);
                st4(&g_X[idx], x);    st4(&g_G1[idx], g1n);
                st4(&g_G21[idx], g21n); st4(&g_G22[idx], g22n);
            }
            __syncthreads();
        }
        m1d *= 1.05; m2d *= 1.05;
    }
}

// ======================= launcher =======================
extern "C" void kernel_launch(void* const* d_in, const int* in_sizes, int n_in,
                              void* d_out, int out_size) {
    const float* Y   = (const float*)d_in[0];
    const float* inW = (const float*)d_in[1];
    float* out = (float*)d_out;

    cudaFuncSetAttribute(hwtv_fused, cudaFuncAttributeMaxDynamicSharedMemorySize, SMEM_BYTES);

    init_q_kernel<<<128, 128>>>();
    hwtv_fused<<<NIMG, NTHR, SMEM_BYTES>>>(Y, inW, out);
}